// round 4
// baseline (speedup 1.0000x reference)
#include <cuda_runtime.h>
#include <math_constants.h>

#define NF    1024
#define NK    (NF + 1)
#define ND    256               // output units per side
#define NOUT  512
#define RPB   4                 // rows per block (main kernel)
#define NBLK  256               // main grid: 256 blocks * 4 rows = 1024 rows
#define SBLK  256               // spread grid
#define W4    (NK * ND / 4)     // 65600 float4 per weight matrix
#define CAP   128               // per-row candidate capacity (overflow -> exact fallback)

// Per-block spread partials: [block][ {dmax, dmin, emax, emin} ].
// Plain deterministic overwrite every launch -> no reset, no atomics, graph-safe.
__device__ float4 g_part[SBLK];

__device__ __forceinline__ float wmax(float v) {
    #pragma unroll
    for (int o = 16; o > 0; o >>= 1) v = fmaxf(v, __shfl_xor_sync(0xffffffffu, v, o));
    return v;
}
__device__ __forceinline__ float wmin(float v) {
    #pragma unroll
    for (int o = 16; o > 0; o >>= 1) v = fminf(v, __shfl_xor_sync(0xffffffffu, v, o));
    return v;
}

// ---------------------------------------------------------------------------
// Kernel 1: per-block partial max/min of both weight matrices (float4 loads).
// ---------------------------------------------------------------------------
__global__ __launch_bounds__(256) void spread_partial(
    const float4* __restrict__ dil4, const float4* __restrict__ ero4)
{
    const int tid = threadIdx.x;
    const int i   = blockIdx.x * 256 + tid;          // 0..65535

    float4 d = dil4[i], e = ero4[i];
    float dmx = fmaxf(fmaxf(d.x, d.y), fmaxf(d.z, d.w));
    float dmn = fminf(fminf(d.x, d.y), fminf(d.z, d.w));
    float emx = fmaxf(fmaxf(e.x, e.y), fmaxf(e.z, e.w));
    float emn = fminf(fminf(e.x, e.y), fminf(e.z, e.w));

    if (i < W4 - 65536) {                            // 64-float4 tail
        float4 d2 = dil4[i + 65536], e2 = ero4[i + 65536];
        dmx = fmaxf(dmx, fmaxf(fmaxf(d2.x, d2.y), fmaxf(d2.z, d2.w)));
        dmn = fminf(dmn, fminf(fminf(d2.x, d2.y), fminf(d2.z, d2.w)));
        emx = fmaxf(emx, fmaxf(fmaxf(e2.x, e2.y), fmaxf(e2.z, e2.w)));
        emn = fminf(emn, fminf(fminf(e2.x, e2.y), fminf(e2.z, e2.w)));
    }

    __shared__ float s[4][8];
    dmx = wmax(dmx); dmn = wmin(dmn); emx = wmax(emx); emn = wmin(emn);
    const int w = tid >> 5, l = tid & 31;
    if (l == 0) { s[0][w] = dmx; s[1][w] = dmn; s[2][w] = emx; s[3][w] = emn; }
    __syncthreads();
    if (w == 0) {
        dmx = (l < 8) ? s[0][l] : -CUDART_INF_F;  dmx = wmax(dmx);
        dmn = (l < 8) ? s[1][l] :  CUDART_INF_F;  dmn = wmin(dmn);
        emx = (l < 8) ? s[2][l] : -CUDART_INF_F;  emx = wmax(emx);
        emn = (l < 8) ? s[3][l] :  CUDART_INF_F;  emn = wmin(emn);
        if (l == 0) g_part[blockIdx.x] = make_float4(dmx, dmn, emx, emn);
    }
}

// ---------------------------------------------------------------------------
// Kernel 2: 4 batch rows per block. Each block re-reduces the 256 spread
// partials itself (L2 broadcast, hidden behind the x-row loads), then does
// exact-pruned tropical matmul:
//   dilation argmax k requires  x[k] >= xmax - (Dmax-Dmin)
//   erosion  argmin k requires  x[k] <= xmin + (Emax-Emin)
// ---------------------------------------------------------------------------
__global__ __launch_bounds__(256) void dilate_erode_main(
    const float* __restrict__ x,
    const float* __restrict__ dil,
    const float* __restrict__ ero,
    float* __restrict__ out)
{
    __shared__ float s_sp[4][8];          // spread partial block-reduce
    __shared__ float s_r[RPB][2][8];      // per-row max/min partials
    __shared__ float s_spread[2];         // {spreadD, spreadE}
    __shared__ float s_ext[RPB][2];       // {xmax, xmin} per row
    __shared__ int   nD[RPB], nE[RPB];
    __shared__ int   kD[RPB][CAP], kE[RPB][CAP];
    __shared__ float vD[RPB][CAP], vE[RPB][CAP];

    const int tid = threadIdx.x;
    const int b0  = blockIdx.x * RPB;
    const int w   = tid >> 5, l = tid & 31;

    if (tid < RPB) { nD[tid] = 0; nE[tid] = 0; }

    // ---- issue all global loads first (MLP = 5 x float4) ----
    const float4* __restrict__ x4 = (const float4*)x;
    float4 f[RPB];
    #pragma unroll
    for (int r = 0; r < RPB; r++)
        f[r] = x4[(size_t)(b0 + r) * 256 + tid];     // features k = tid*4..tid*4+3
    const float4 g = g_part[tid];                    // spread partial slot

    // ---- spread reduce (warp level) ----
    float dmx = wmax(g.x), dmn = wmin(g.y), emx = wmax(g.z), emn = wmin(g.w);
    if (l == 0) { s_sp[0][w] = dmx; s_sp[1][w] = dmn; s_sp[2][w] = emx; s_sp[3][w] = emn; }

    // ---- per-row extrema (bias value 0 folded into init) ----
    #pragma unroll
    for (int r = 0; r < RPB; r++) {
        float mx = fmaxf(0.0f, fmaxf(fmaxf(f[r].x, f[r].y), fmaxf(f[r].z, f[r].w)));
        float mn = fminf(0.0f, fminf(fminf(f[r].x, f[r].y), fminf(f[r].z, f[r].w)));
        mx = wmax(mx); mn = wmin(mn);
        if (l == 0) { s_r[r][0][w] = mx; s_r[r][1][w] = mn; }
    }
    __syncthreads();

    // ---- finalize reductions: warp 0 -> spreads, warps 1..4 -> rows ----
    if (w == 0) {
        dmx = (l < 8) ? s_sp[0][l] : -CUDART_INF_F;  dmx = wmax(dmx);
        dmn = (l < 8) ? s_sp[1][l] :  CUDART_INF_F;  dmn = wmin(dmn);
        emx = (l < 8) ? s_sp[2][l] : -CUDART_INF_F;  emx = wmax(emx);
        emn = (l < 8) ? s_sp[3][l] :  CUDART_INF_F;  emn = wmin(emn);
        if (l == 0) { s_spread[0] = dmx - dmn; s_spread[1] = emx - emn; }
    } else if (w <= RPB) {
        const int r = w - 1;
        float mx = (l < 8) ? s_r[r][0][l] : -CUDART_INF_F;  mx = wmax(mx);
        float mn = (l < 8) ? s_r[r][1][l] :  CUDART_INF_F;  mn = wmin(mn);
        if (l == 0) { s_ext[r][0] = mx; s_ext[r][1] = mn; }
    }
    __syncthreads();

    const float spreadD = s_spread[0];
    const float spreadE = s_spread[1];

    // ---- candidate scan (inclusive thresholds -> exact) ----
    #pragma unroll
    for (int r = 0; r < RPB; r++) {
        const float thD = s_ext[r][0] - spreadD;
        const float thE = s_ext[r][1] + spreadE;
        float vv[4] = { f[r].x, f[r].y, f[r].z, f[r].w };
        #pragma unroll
        for (int q = 0; q < 4; q++) {
            const int k = tid * 4 + q;
            if (vv[q] >= thD) { int p = atomicAdd(&nD[r], 1); if (p < CAP) { kD[r][p] = k; vD[r][p] = vv[q]; } }
            if (vv[q] <= thE) { int p = atomicAdd(&nE[r], 1); if (p < CAP) { kE[r][p] = k; vE[r][p] = vv[q]; } }
        }
        if (tid == 0) {          // bias feature k = NF, value 0
            if (0.0f >= thD) { int p = atomicAdd(&nD[r], 1); if (p < CAP) { kD[r][p] = NF; vD[r][p] = 0.0f; } }
            if (0.0f <= thE) { int p = atomicAdd(&nE[r], 1); if (p < CAP) { kE[r][p] = NF; vE[r][p] = 0.0f; } }
        }
    }
    __syncthreads();

    // ---- accumulate & store: thread owns output column j = tid ----
    #pragma unroll
    for (int r = 0; r < RPB; r++) {
        const int cD = nD[r], cE = nE[r];

        float dv = -CUDART_INF_F;
        if (cD <= CAP) {
            for (int c = 0; c < cD; c++)
                dv = fmaxf(dv, vD[r][c] + dil[kD[r][c] * ND + tid]);
        } else {                  // exact fallback (never expected)
            for (int k = 0; k < NK; k++) {
                float xv = (k < NF) ? x[(size_t)(b0 + r) * NF + k] : 0.0f;
                dv = fmaxf(dv, xv + dil[k * ND + tid]);
            }
        }

        float ev = CUDART_INF_F;
        if (cE <= CAP) {
            for (int c = 0; c < cE; c++)
                ev = fminf(ev, vE[r][c] - ero[kE[r][c] * ND + tid]);
        } else {
            for (int k = 0; k < NK; k++) {
                float xv = (k < NF) ? x[(size_t)(b0 + r) * NF + k] : 0.0f;
                ev = fminf(ev, xv - ero[k * ND + tid]);
            }
        }

        out[(size_t)(b0 + r) * NOUT + tid]      = ev;   // eroded  cols [0,256)
        out[(size_t)(b0 + r) * NOUT + ND + tid] = dv;   // dilated cols [256,512)
    }
}

extern "C" void kernel_launch(void* const* d_in, const int* in_sizes, int n_in,
                              void* d_out, int out_size)
{
    (void)in_sizes; (void)n_in; (void)out_size;
    const float* x   = (const float*)d_in[0];
    const float* dil = (const float*)d_in[1];
    const float* ero = (const float*)d_in[2];
    float* out = (float*)d_out;

    spread_partial<<<SBLK, 256>>>((const float4*)dil, (const float4*)ero);
    dilate_erode_main<<<NBLK, 256>>>(x, dil, ero, out);
}

// round 5
// speedup vs baseline: 1.0152x; 1.0152x over previous
#include <cuda_runtime.h>
#include <math_constants.h>

#define NF    1024
#define NK    (NF + 1)
#define ND    256               // output units per side
#define NOUT  512
#define NBLK  1024              // both kernels: 1024 blocks
#define W4    (NK * ND / 4)     // 65600 float4 per weight matrix
#define WCH   64                // weight float4s per block per matrix (65536/1024)
#define CAP   128               // candidate capacity (overflow -> exact fallback)

// Deterministic per-launch overwrites: no reset node, no atomics, graph-safe.
__device__ float2 g_xext[NBLK];    // {xmax, xmin} per batch row (bias 0 folded in)
__device__ float4 g_wpart[NBLK];   // {dmax, dmin, emax, emin} weight partial per block

__device__ __forceinline__ float wmax(float v) {
    #pragma unroll
    for (int o = 16; o > 0; o >>= 1) v = fmaxf(v, __shfl_xor_sync(0xffffffffu, v, o));
    return v;
}
__device__ __forceinline__ float wmin(float v) {
    #pragma unroll
    for (int o = 16; o > 0; o >>= 1) v = fminf(v, __shfl_xor_sync(0xffffffffu, v, o));
    return v;
}

// ---------------------------------------------------------------------------
// Kernel 1 (prep): block b
//   - reduces x row b -> g_xext[b]
//   - reduces weight chunk [b*64, b*64+64) of BOTH matrices (+ 64-elem tails
//     handled one-per-block by blocks 0..63) -> g_wpart[b]
// Pure streaming: pulls all DRAM traffic (x 4MB + weights 2MB) at full grid.
// ---------------------------------------------------------------------------
__global__ __launch_bounds__(256) void prep_kernel(
    const float4* __restrict__ x4,
    const float4* __restrict__ dil4,
    const float4* __restrict__ ero4)
{
    const int tid = threadIdx.x;
    const int b   = blockIdx.x;
    const int w   = tid >> 5, l = tid & 31;

    // x row (features k = tid*4 .. tid*4+3); bias value 0 folded into init
    const float4 f = x4[b * 256 + tid];
    float xmx = fmaxf(0.0f, fmaxf(fmaxf(f.x, f.y), fmaxf(f.z, f.w)));
    float xmn = fminf(0.0f, fminf(fminf(f.x, f.y), fminf(f.z, f.w)));

    // weight chunk
    float dmx = -CUDART_INF_F, dmn = CUDART_INF_F;
    float emx = -CUDART_INF_F, emn = CUDART_INF_F;
    if (tid < WCH) {
        float4 d = dil4[b * WCH + tid];
        dmx = fmaxf(fmaxf(d.x, d.y), fmaxf(d.z, d.w));
        dmn = fminf(fminf(d.x, d.y), fminf(d.z, d.w));
    } else if (tid < 2 * WCH) {
        float4 e = ero4[b * WCH + (tid - WCH)];
        emx = fmaxf(fmaxf(e.x, e.y), fmaxf(e.z, e.w));
        emn = fminf(fminf(e.x, e.y), fminf(e.z, e.w));
    } else if (tid == 2 * WCH && b < W4 - NBLK * WCH) {     // dil tail (64 elems)
        float4 d = dil4[NBLK * WCH + b];
        dmx = fmaxf(fmaxf(d.x, d.y), fmaxf(d.z, d.w));
        dmn = fminf(fminf(d.x, d.y), fminf(d.z, d.w));
    } else if (tid == 2 * WCH + 1 && b < W4 - NBLK * WCH) { // ero tail
        float4 e = ero4[NBLK * WCH + b];
        emx = fmaxf(fmaxf(e.x, e.y), fmaxf(e.z, e.w));
        emn = fminf(fminf(e.x, e.y), fminf(e.z, e.w));
    }

    __shared__ float s[6][8];
    xmx = wmax(xmx); xmn = wmin(xmn);
    dmx = wmax(dmx); dmn = wmin(dmn);
    emx = wmax(emx); emn = wmin(emn);
    if (l == 0) {
        s[0][w] = xmx; s[1][w] = xmn; s[2][w] = dmx;
        s[3][w] = dmn; s[4][w] = emx; s[5][w] = emn;
    }
    __syncthreads();
    if (w == 0) {
        xmx = (l < 8) ? s[0][l] : -CUDART_INF_F;  xmx = wmax(xmx);
        xmn = (l < 8) ? s[1][l] :  CUDART_INF_F;  xmn = wmin(xmn);
        dmx = (l < 8) ? s[2][l] : -CUDART_INF_F;  dmx = wmax(dmx);
        dmn = (l < 8) ? s[3][l] :  CUDART_INF_F;  dmn = wmin(dmn);
        emx = (l < 8) ? s[4][l] : -CUDART_INF_F;  emx = wmax(emx);
        emn = (l < 8) ? s[5][l] :  CUDART_INF_F;  emn = wmin(emn);
        if (l == 0) {
            g_xext[b]  = make_float2(xmx, xmn);
            g_wpart[b] = make_float4(dmx, dmn, emx, emn);
        }
    }
}

// ---------------------------------------------------------------------------
// Kernel 2 (main): block b — everything it touches is L2-resident (prep just
// streamed x and the weights). Exact pruning:
//   dilation argmax k needs  x[k] >= xmax - (Dmax-Dmin)
//   erosion  argmin k needs  x[k] <= xmin + (Emax-Emin)
// ---------------------------------------------------------------------------
__global__ __launch_bounds__(256) void dilate_erode_main(
    const float* __restrict__ x,
    const float* __restrict__ dil,
    const float* __restrict__ ero,
    float* __restrict__ out)
{
    __shared__ float s[4][8];
    __shared__ float s_spread[2];
    __shared__ int   nD, nE;
    __shared__ int   kD[CAP], kE[CAP];
    __shared__ float vD[CAP], vE[CAP];

    const int tid = threadIdx.x;
    const int b   = blockIdx.x;
    const int w   = tid >> 5, l = tid & 31;

    if (tid == 0) { nD = 0; nE = 0; }

    // ---- issue all loads up front (all L2 hits) ----
    const float4 f  = ((const float4*)x)[b * 256 + tid];   // features tid*4..+3
    float4 p[4];
    #pragma unroll
    for (int i = 0; i < 4; i++) p[i] = g_wpart[tid * 4 + i];
    const float2 xe = g_xext[b];                            // broadcast

    // ---- global weight spread: reduce 1024 partials ----
    float dmx = fmaxf(fmaxf(p[0].x, p[1].x), fmaxf(p[2].x, p[3].x));
    float dmn = fminf(fminf(p[0].y, p[1].y), fminf(p[2].y, p[3].y));
    float emx = fmaxf(fmaxf(p[0].z, p[1].z), fmaxf(p[2].z, p[3].z));
    float emn = fminf(fminf(p[0].w, p[1].w), fminf(p[2].w, p[3].w));
    dmx = wmax(dmx); dmn = wmin(dmn); emx = wmax(emx); emn = wmin(emn);
    if (l == 0) { s[0][w] = dmx; s[1][w] = dmn; s[2][w] = emx; s[3][w] = emn; }
    __syncthreads();
    if (w == 0) {
        dmx = (l < 8) ? s[0][l] : -CUDART_INF_F;  dmx = wmax(dmx);
        dmn = (l < 8) ? s[1][l] :  CUDART_INF_F;  dmn = wmin(dmn);
        emx = (l < 8) ? s[2][l] : -CUDART_INF_F;  emx = wmax(emx);
        emn = (l < 8) ? s[3][l] :  CUDART_INF_F;  emn = wmin(emn);
        if (l == 0) { s_spread[0] = dmx - dmn; s_spread[1] = emx - emn; }
    }
    __syncthreads();

    const float thD = xe.x - s_spread[0];   // inclusive -> exact
    const float thE = xe.y + s_spread[1];

    // ---- candidate scan ----
    {
        float vv[4] = { f.x, f.y, f.z, f.w };
        #pragma unroll
        for (int q = 0; q < 4; q++) {
            const int k = tid * 4 + q;
            if (vv[q] >= thD) { int pD = atomicAdd(&nD, 1); if (pD < CAP) { kD[pD] = k; vD[pD] = vv[q]; } }
            if (vv[q] <= thE) { int pE = atomicAdd(&nE, 1); if (pE < CAP) { kE[pE] = k; vE[pE] = vv[q]; } }
        }
        if (tid == 0) {   // bias feature k = NF, value 0
            if (0.0f >= thD) { int pD = atomicAdd(&nD, 1); if (pD < CAP) { kD[pD] = NF; vD[pD] = 0.0f; } }
            if (0.0f <= thE) { int pE = atomicAdd(&nE, 1); if (pE < CAP) { kE[pE] = NF; vE[pE] = 0.0f; } }
        }
    }
    __syncthreads();

    const int cD = nD, cE = nE;

    // ---- gather & accumulate: thread owns output column j = tid ----
    float dv = -CUDART_INF_F;
    if (cD <= CAP) {
        for (int c = 0; c < cD; c++)
            dv = fmaxf(dv, vD[c] + dil[kD[c] * ND + tid]);
    } else {                      // exact fallback (never expected)
        for (int k = 0; k < NK; k++) {
            float xv = (k < NF) ? x[(size_t)b * NF + k] : 0.0f;
            dv = fmaxf(dv, xv + dil[k * ND + tid]);
        }
    }

    float ev = CUDART_INF_F;
    if (cE <= CAP) {
        for (int c = 0; c < cE; c++)
            ev = fminf(ev, vE[c] - ero[kE[c] * ND + tid]);
    } else {
        for (int k = 0; k < NK; k++) {
            float xv = (k < NF) ? x[(size_t)b * NF + k] : 0.0f;
            ev = fminf(ev, xv - ero[k * ND + tid]);
        }
    }

    out[(size_t)b * NOUT + tid]      = ev;   // eroded  cols [0,256)
    out[(size_t)b * NOUT + ND + tid] = dv;   // dilated cols [256,512)
}

extern "C" void kernel_launch(void* const* d_in, const int* in_sizes, int n_in,
                              void* d_out, int out_size)
{
    (void)in_sizes; (void)n_in; (void)out_size;
    const float* x   = (const float*)d_in[0];
    const float* dil = (const float*)d_in[1];
    const float* ero = (const float*)d_in[2];
    float* out = (float*)d_out;

    prep_kernel<<<NBLK, 256>>>((const float4*)x, (const float4*)dil, (const float4*)ero);
    dilate_erode_main<<<NBLK, 256>>>(x, dil, ero, out);
}